// round 4
// baseline (speedup 1.0000x reference)
#include <cuda_runtime.h>
#include <cuda_fp16.h>
#include <mma.h>
#include <math.h>

using namespace nvcuda;

#define DIM 128
#define MAX_N 100000
#define MAX_E 3200000
#define STILE 1024
#define MAX_TILES 128   // ceil(100000/1024)=98

// ---------------- scratch (static device globals; no allocation) ----------------
__device__ __align__(16) __half g_Yh[(size_t)MAX_N * DIM];  // 25.6 MB fp16 Y
__device__ int   g_rowptr[MAX_N + 1];
__device__ int   g_cursor[MAX_N];
__device__ int2  g_edge[MAX_E];              // 25.6 MB  row-sorted (col, val-bits)
__device__ int   g_bsum[MAX_TILES];
__device__ int   g_boff[MAX_TILES];

// ---------------- 1) GEMM (tensor cores, TF32): Y = X @ W^T + b -> fp16 --------
// Block: 64 rows x 128 cols, 256 threads = 8 warps (4 in m, 2 in n).
// X tile staged via smem (zero-padded tail). W read col-major straight from gmem.
__global__ __launch_bounds__(256) void gemm_wmma_kernel(
    const float* __restrict__ X, const float* __restrict__ W,
    const float* __restrict__ bias, int N)
{
    __shared__ __align__(16) float S[64 * 128];   // X tile, reused for output

    const int tid  = threadIdx.x;
    const int warp = tid >> 5;
    const int wm   = warp & 3;          // 0..3 -> m offset 16*wm
    const int wn   = warp >> 2;         // 0..1 -> n offset 64*wn
    const int mb   = blockIdx.x * 64;

    // ---- stage X[mb:mb+64, 0:128] into smem (zero-pad OOB rows) ----
    {
        float4* S4 = (float4*)S;
        const float4* X4 = (const float4*)X;
#pragma unroll
        for (int i = 0; i < 8; i++) {
            int idx  = tid + i * 256;           // float4 index within tile (0..2047)
            int row  = idx >> 5;                // 32 float4 per row
            int grow = mb + row;
            S4[idx] = (grow < N) ? X4[(size_t)grow * 32 + (idx & 31)]
                                 : make_float4(0.f, 0.f, 0.f, 0.f);
        }
    }
    __syncthreads();

    wmma::fragment<wmma::accumulator, 16, 16, 8, float> acc[4];
#pragma unroll
    for (int j = 0; j < 4; j++) wmma::fill_fragment(acc[j], 0.f);

    const int n0 = wn * 64;

#pragma unroll
    for (int k0 = 0; k0 < DIM; k0 += 8) {
        wmma::fragment<wmma::matrix_a, 16, 16, 8, wmma::precision::tf32, wmma::row_major> a;
        wmma::load_matrix_sync(a, &S[wm * 16 * 128 + k0], 128);
#pragma unroll
        for (int t = 0; t < a.num_elements; t++) a.x[t] = wmma::__float_to_tf32(a.x[t]);

#pragma unroll
        for (int j = 0; j < 4; j++) {
            wmma::fragment<wmma::matrix_b, 16, 16, 8, wmma::precision::tf32, wmma::col_major> bf;
            // B[k][n] = W[n*128 + k]; tile origin (k0, n0+16j), ld=128, col-major
            wmma::load_matrix_sync(bf, &W[(size_t)(n0 + j * 16) * 128 + k0], 128);
#pragma unroll
            for (int t = 0; t < bf.num_elements; t++) bf.x[t] = wmma::__float_to_tf32(bf.x[t]);
            wmma::mma_sync(acc[j], a, bf, acc[j]);
        }
    }

    __syncthreads();   // everyone done reading X tile; reuse S for the output tile

#pragma unroll
    for (int j = 0; j < 4; j++)
        wmma::store_matrix_sync(&S[wm * 16 * 128 + n0 + j * 16], acc[j], 128,
                                wmma::mem_row_major);
    __syncthreads();

    // ---- epilogue: bias + fp16 pack; each thread owns 1 row x 32 cols ----
    {
        int r    = tid >> 2;
        int c0   = (tid & 3) * 32;
        int grow = mb + r;
        if (grow < N) {
#pragma unroll
            for (int c = 0; c < 32; c += 8) {
                const float* src = &S[r * 128 + c0 + c];
                const float* bsrc = &bias[c0 + c];
                __half2 h[4];
                h[0] = __floats2half2_rn(src[0] + bsrc[0], src[1] + bsrc[1]);
                h[1] = __floats2half2_rn(src[2] + bsrc[2], src[3] + bsrc[3]);
                h[2] = __floats2half2_rn(src[4] + bsrc[4], src[5] + bsrc[5]);
                h[3] = __floats2half2_rn(src[6] + bsrc[6], src[7] + bsrc[7]);
                *(uint4*)&g_Yh[(size_t)grow * DIM + c0 + c] = *(uint4*)h;
            }
        }
    }
}

// ---------------- 2) CSR build -----------------------------------------------
__global__ void zero_cnt_kernel(int N) {
    int i = blockIdx.x * blockDim.x + threadIdx.x;
    if (i < N) g_cursor[i] = 0;
}

__global__ void hist_kernel(const int* __restrict__ rows, int E) {
    int t = blockIdx.x * blockDim.x + threadIdx.x;
    int e = t * 4;
    if (e + 3 < E) {
        int4 r = *(const int4*)&rows[e];
        atomicAdd(&g_cursor[r.x], 1);
        atomicAdd(&g_cursor[r.y], 1);
        atomicAdd(&g_cursor[r.z], 1);
        atomicAdd(&g_cursor[r.w], 1);
    } else {
        for (int k = e; k < E; k++) atomicAdd(&g_cursor[rows[k]], 1);
    }
}

__global__ __launch_bounds__(256) void reduce_tile_kernel(int N) {
    __shared__ int s[8];
    int b = blockIdx.x, t = threadIdx.x;
    int base = b * STILE;
    int sum = 0;
#pragma unroll
    for (int i = t; i < STILE; i += 256) {
        int idx = base + i;
        sum += (idx < N) ? g_cursor[idx] : 0;
    }
#pragma unroll
    for (int off = 16; off; off >>= 1)
        sum += __shfl_down_sync(0xffffffffu, sum, off);
    if ((t & 31) == 0) s[t >> 5] = sum;
    __syncthreads();
    if (t < 8) {
        sum = s[t];
#pragma unroll
        for (int off = 4; off; off >>= 1)
            sum += __shfl_down_sync(0xffu, sum, off);
        if (t == 0) g_bsum[b] = sum;
    }
}

__global__ __launch_bounds__(128) void scan_tops_kernel(int nb, int N) {
    __shared__ int s[128];
    int t = threadIdx.x;
    int v = (t < nb) ? g_bsum[t] : 0;
    s[t] = v;
    __syncthreads();
#pragma unroll
    for (int off = 1; off < 128; off <<= 1) {
        int u = (t >= off) ? s[t - off] : 0;
        __syncthreads();
        s[t] += u;
        __syncthreads();
    }
    if (t < nb) g_boff[t] = s[t] - v;
    if (t == nb - 1) g_rowptr[N] = s[t];
}

__global__ __launch_bounds__(STILE) void scan_tile_kernel(int N) {
    __shared__ int s[STILE];
    int b = blockIdx.x, t = threadIdx.x;
    int idx = b * STILE + t;
    int v = (idx < N) ? g_cursor[idx] : 0;
    s[t] = v;
    __syncthreads();
#pragma unroll
    for (int off = 1; off < STILE; off <<= 1) {
        int u = (t >= off) ? s[t - off] : 0;
        __syncthreads();
        s[t] += u;
        __syncthreads();
    }
    if (idx < N) {
        int excl = s[t] - v + g_boff[b];
        g_rowptr[idx] = excl;
        g_cursor[idx] = excl;
    }
}

__global__ void scatter_kernel(const int* __restrict__ rows,
                               const int* __restrict__ cols,
                               const float* __restrict__ vals, int E) {
    int t = blockIdx.x * blockDim.x + threadIdx.x;
    int e = t * 4;
    if (e + 3 < E) {
        int4   r = *(const int4*)&rows[e];
        int4   c = *(const int4*)&cols[e];
        float4 v = *(const float4*)&vals[e];
        int p0 = atomicAdd(&g_cursor[r.x], 1);
        int p1 = atomicAdd(&g_cursor[r.y], 1);
        int p2 = atomicAdd(&g_cursor[r.z], 1);
        int p3 = atomicAdd(&g_cursor[r.w], 1);
        g_edge[p0] = make_int2(c.x, __float_as_int(v.x));
        g_edge[p1] = make_int2(c.y, __float_as_int(v.y));
        g_edge[p2] = make_int2(c.z, __float_as_int(v.z));
        g_edge[p3] = make_int2(c.w, __float_as_int(v.w));
    } else {
        for (int k = e; k < E; k++) {
            int pos = atomicAdd(&g_cursor[rows[k]], 1);
            g_edge[pos] = make_int2(cols[k], __float_as_int(vals[k]));
        }
    }
}

// ---------------- 3) SpMM + ELU: one warp per output row, fp16 gather ----------
__global__ __launch_bounds__(256) void spmm_elu_kernel(float* __restrict__ out, int N) {
    int warp = (blockIdx.x * blockDim.x + threadIdx.x) >> 5;
    int lane = threadIdx.x & 31;
    if (warp >= N) return;

    int start = g_rowptr[warp];
    int end   = g_rowptr[warp + 1];

    const uint2* __restrict__ Yh = (const uint2*)g_Yh;
    float4 acc = make_float4(0.f, 0.f, 0.f, 0.f);

    int i = start;
    for (; i + 1 < end; i += 2) {
        int2 e0 = g_edge[i];
        int2 e1 = g_edge[i + 1];
        uint2 r0 = Yh[(size_t)e0.x * 32 + lane];
        uint2 r1 = Yh[(size_t)e1.x * 32 + lane];
        float v0 = __int_as_float(e0.y);
        float v1 = __int_as_float(e1.y);
        float2 a0 = __half22float2(*(const __half2*)&r0.x);
        float2 b0 = __half22float2(*(const __half2*)&r0.y);
        float2 a1 = __half22float2(*(const __half2*)&r1.x);
        float2 b1 = __half22float2(*(const __half2*)&r1.y);
        acc.x += v0 * a0.x + v1 * a1.x;
        acc.y += v0 * a0.y + v1 * a1.y;
        acc.z += v0 * b0.x + v1 * b1.x;
        acc.w += v0 * b0.y + v1 * b1.y;
    }
    if (i < end) {
        int2 e0 = g_edge[i];
        uint2 r0 = Yh[(size_t)e0.x * 32 + lane];
        float v0 = __int_as_float(e0.y);
        float2 a0 = __half22float2(*(const __half2*)&r0.x);
        float2 b0 = __half22float2(*(const __half2*)&r0.y);
        acc.x += v0 * a0.x;
        acc.y += v0 * a0.y;
        acc.z += v0 * b0.x;
        acc.w += v0 * b0.y;
    }

    acc.x = acc.x > 0.f ? acc.x : expm1f(acc.x);
    acc.y = acc.y > 0.f ? acc.y : expm1f(acc.y);
    acc.z = acc.z > 0.f ? acc.z : expm1f(acc.z);
    acc.w = acc.w > 0.f ? acc.w : expm1f(acc.w);

    ((float4*)out)[(size_t)warp * 32 + lane] = acc;
}

// ---------------- launch ---------------------------------------------------------
extern "C" void kernel_launch(void* const* d_in, const int* in_sizes, int n_in,
                              void* d_out, int out_size) {
    const float* x    = (const float*)d_in[0];
    const float* W    = (const float*)d_in[1];
    const float* b    = (const float*)d_in[2];
    const int*   rows = (const int*)d_in[3];
    const int*   cols = (const int*)d_in[4];
    const float* vals = (const float*)d_in[5];
    float* out = (float*)d_out;

    int N = in_sizes[0] / DIM;
    int E = in_sizes[3];
    int nb = (N + STILE - 1) / STILE;
    int e4 = (E + 3) / 4;

    cudaStream_t s1;
    cudaStreamCreateWithFlags(&s1, cudaStreamNonBlocking);
    cudaEvent_t evFork, evJoin;
    cudaEventCreateWithFlags(&evFork, cudaEventDisableTiming);
    cudaEventCreateWithFlags(&evJoin, cudaEventDisableTiming);

    cudaEventRecord(evFork, 0);
    cudaStreamWaitEvent(s1, evFork, 0);

    // CSR build chain on side stream
    zero_cnt_kernel<<<(N + 255) / 256, 256, 0, s1>>>(N);
    hist_kernel<<<(e4 + 255) / 256, 256, 0, s1>>>(rows, E);
    reduce_tile_kernel<<<nb, 256, 0, s1>>>(N);
    scan_tops_kernel<<<1, 128, 0, s1>>>(nb, N);
    scan_tile_kernel<<<nb, STILE, 0, s1>>>(N);
    scatter_kernel<<<(e4 + 255) / 256, 256, 0, s1>>>(rows, cols, vals, E);

    // GEMM (tensor cores) on main stream, concurrent with CSR build
    gemm_wmma_kernel<<<(N + 63) / 64, 256>>>(x, W, b, N);

    cudaEventRecord(evJoin, s1);
    cudaStreamWaitEvent(0, evJoin, 0);

    spmm_elu_kernel<<<((size_t)N * 32 + 255) / 256, 256>>>(out, N);
}

// round 5
// speedup vs baseline: 1.2230x; 1.2230x over previous
#include <cuda_runtime.h>
#include <cuda_fp16.h>
#include <mma.h>
#include <math.h>

using namespace nvcuda;

#define DIM 128
#define MAX_N 100000
#define MAX_E 3200000
#define STILE 1024
#define MAX_TILES 128   // ceil(100000/1024)=98

// ---------------- scratch (static device globals; no allocation) ----------------
__device__ __align__(16) __half g_Yh[(size_t)MAX_N * DIM];  // 25.6 MB fp16 Y
__device__ int   g_rowptr[MAX_N + 1];
__device__ int   g_cursor[MAX_N];
__device__ int2  g_edge[MAX_E];              // 25.6 MB  row-sorted (col, val-bits)
__device__ int   g_bsum[MAX_TILES];
__device__ int   g_boff[MAX_TILES];

// ---------------- 1) GEMM (fp16 tensor cores): Y = X @ W^T + b -> fp16 ---------
// Block: 64 rows x 128 cols, 256 threads = 8 warps (4 in m, 2 in n).
// X tile AND full W staged in smem as fp16 (coalesced float4 loads + convert).
// Smem (48KB) union-reused as fp32 staging for the epilogue.
__global__ __launch_bounds__(256) void gemm_h_kernel(
    const float* __restrict__ X, const float* __restrict__ W,
    const float* __restrict__ bias, int N)
{
    __shared__ __align__(16) char sraw[49152];
    __half* Xh = (__half*)sraw;             // [64][128]  = 16 KB
    __half* Wh = (__half*)(sraw + 16384);   // [128][128] = 32 KB  (row n, col k)
    float*  So = (float*)sraw;              // epilogue [64][128] fp32 = 32 KB

    const int tid  = threadIdx.x;
    const int warp = tid >> 5;
    const int wm   = warp & 3;              // m-tile (16 rows each)
    const int wn   = warp >> 2;             // n-half (64 cols each)
    const int mb   = blockIdx.x * 64;

    // ---- stage W[128][128] fp32 -> fp16 smem (coalesced) ----
    {
        const float4* W4 = (const float4*)W;
        __half2* Wh2 = (__half2*)Wh;
#pragma unroll
        for (int i = 0; i < 16; i++) {
            int idx = tid + i * 256;        // float4 index, 0..4095
            float4 f = W4[idx];
            Wh2[idx * 2]     = __floats2half2_rn(f.x, f.y);
            Wh2[idx * 2 + 1] = __floats2half2_rn(f.z, f.w);
        }
    }
    // ---- stage X[mb:mb+64][128] fp32 -> fp16 smem (zero-pad OOB rows) ----
    {
        const float4* X4 = (const float4*)X;
        __half2* Xh2 = (__half2*)Xh;
#pragma unroll
        for (int i = 0; i < 8; i++) {
            int idx  = tid + i * 256;       // float4 index, 0..2047
            int row  = idx >> 5;            // 32 float4 per row
            int grow = mb + row;
            float4 f = (grow < N) ? X4[(size_t)grow * 32 + (idx & 31)]
                                  : make_float4(0.f, 0.f, 0.f, 0.f);
            Xh2[idx * 2]     = __floats2half2_rn(f.x, f.y);
            Xh2[idx * 2 + 1] = __floats2half2_rn(f.z, f.w);
        }
    }
    __syncthreads();

    wmma::fragment<wmma::accumulator, 16, 16, 16, float> acc[4];
#pragma unroll
    for (int j = 0; j < 4; j++) wmma::fill_fragment(acc[j], 0.f);

#pragma unroll
    for (int k0 = 0; k0 < DIM; k0 += 16) {
        wmma::fragment<wmma::matrix_a, 16, 16, 16, __half, wmma::row_major> a;
        wmma::load_matrix_sync(a, &Xh[wm * 16 * 128 + k0], 128);
#pragma unroll
        for (int j = 0; j < 4; j++) {
            wmma::fragment<wmma::matrix_b, 16, 16, 16, __half, wmma::col_major> bf;
            // B(k,n) = Wh[n*128 + k]; tile origin n = wn*64 + j*16, k = k0
            wmma::load_matrix_sync(bf, &Wh[(wn * 64 + j * 16) * 128 + k0], 128);
            wmma::mma_sync(acc[j], a, bf, acc[j]);
        }
    }
    __syncthreads();   // done reading Xh/Wh; reuse smem for fp32 output staging

#pragma unroll
    for (int j = 0; j < 4; j++)
        wmma::store_matrix_sync(&So[wm * 16 * 128 + wn * 64 + j * 16], acc[j],
                                128, wmma::mem_row_major);
    __syncthreads();

    // ---- epilogue: bias + fp16 pack; each thread owns 1 row x 32 cols ----
    {
        int r    = tid >> 2;
        int c0   = (tid & 3) * 32;
        int grow = mb + r;
        if (grow < N) {
#pragma unroll
            for (int c = 0; c < 32; c += 8) {
                const float* src  = &So[r * 128 + c0 + c];
                const float* bsrc = &bias[c0 + c];
                __half2 h[4];
                h[0] = __floats2half2_rn(src[0] + bsrc[0], src[1] + bsrc[1]);
                h[1] = __floats2half2_rn(src[2] + bsrc[2], src[3] + bsrc[3]);
                h[2] = __floats2half2_rn(src[4] + bsrc[4], src[5] + bsrc[5]);
                h[3] = __floats2half2_rn(src[6] + bsrc[6], src[7] + bsrc[7]);
                *(uint4*)&g_Yh[(size_t)grow * DIM + c0 + c] = *(uint4*)h;
            }
        }
    }
}

// ---------------- 2) CSR build -----------------------------------------------
__global__ void zero_cnt_kernel(int N) {
    int i = blockIdx.x * blockDim.x + threadIdx.x;
    if (i < N) g_cursor[i] = 0;
}

__global__ void hist_kernel(const int* __restrict__ rows, int E) {
    int t = blockIdx.x * blockDim.x + threadIdx.x;
    int e = t * 4;
    if (e + 3 < E) {
        int4 r = *(const int4*)&rows[e];
        atomicAdd(&g_cursor[r.x], 1);
        atomicAdd(&g_cursor[r.y], 1);
        atomicAdd(&g_cursor[r.z], 1);
        atomicAdd(&g_cursor[r.w], 1);
    } else {
        for (int k = e; k < E; k++) atomicAdd(&g_cursor[rows[k]], 1);
    }
}

__global__ __launch_bounds__(256) void reduce_tile_kernel(int N) {
    __shared__ int s[8];
    int b = blockIdx.x, t = threadIdx.x;
    int base = b * STILE;
    int sum = 0;
#pragma unroll
    for (int i = t; i < STILE; i += 256) {
        int idx = base + i;
        sum += (idx < N) ? g_cursor[idx] : 0;
    }
#pragma unroll
    for (int off = 16; off; off >>= 1)
        sum += __shfl_down_sync(0xffffffffu, sum, off);
    if ((t & 31) == 0) s[t >> 5] = sum;
    __syncthreads();
    if (t < 8) {
        sum = s[t];
#pragma unroll
        for (int off = 4; off; off >>= 1)
            sum += __shfl_down_sync(0xffu, sum, off);
        if (t == 0) g_bsum[b] = sum;
    }
}

__global__ __launch_bounds__(128) void scan_tops_kernel(int nb, int N) {
    __shared__ int s[128];
    int t = threadIdx.x;
    int v = (t < nb) ? g_bsum[t] : 0;
    s[t] = v;
    __syncthreads();
#pragma unroll
    for (int off = 1; off < 128; off <<= 1) {
        int u = (t >= off) ? s[t - off] : 0;
        __syncthreads();
        s[t] += u;
        __syncthreads();
    }
    if (t < nb) g_boff[t] = s[t] - v;
    if (t == nb - 1) g_rowptr[N] = s[t];
}

__global__ __launch_bounds__(STILE) void scan_tile_kernel(int N) {
    __shared__ int s[STILE];
    int b = blockIdx.x, t = threadIdx.x;
    int idx = b * STILE + t;
    int v = (idx < N) ? g_cursor[idx] : 0;
    s[t] = v;
    __syncthreads();
#pragma unroll
    for (int off = 1; off < STILE; off <<= 1) {
        int u = (t >= off) ? s[t - off] : 0;
        __syncthreads();
        s[t] += u;
        __syncthreads();
    }
    if (idx < N) {
        int excl = s[t] - v + g_boff[b];
        g_rowptr[idx] = excl;
        g_cursor[idx] = excl;
    }
}

__global__ void scatter_kernel(const int* __restrict__ rows,
                               const int* __restrict__ cols,
                               const float* __restrict__ vals, int E) {
    int t = blockIdx.x * blockDim.x + threadIdx.x;
    int e = t * 4;
    if (e + 3 < E) {
        int4   r = *(const int4*)&rows[e];
        int4   c = *(const int4*)&cols[e];
        float4 v = *(const float4*)&vals[e];
        int p0 = atomicAdd(&g_cursor[r.x], 1);
        int p1 = atomicAdd(&g_cursor[r.y], 1);
        int p2 = atomicAdd(&g_cursor[r.z], 1);
        int p3 = atomicAdd(&g_cursor[r.w], 1);
        g_edge[p0] = make_int2(c.x, __float_as_int(v.x));
        g_edge[p1] = make_int2(c.y, __float_as_int(v.y));
        g_edge[p2] = make_int2(c.z, __float_as_int(v.z));
        g_edge[p3] = make_int2(c.w, __float_as_int(v.w));
    } else {
        for (int k = e; k < E; k++) {
            int pos = atomicAdd(&g_cursor[rows[k]], 1);
            g_edge[pos] = make_int2(cols[k], __float_as_int(vals[k]));
        }
    }
}

// ---------------- 3) SpMM + ELU: one warp per row, fp16 gather, unroll 4 --------
__global__ __launch_bounds__(256) void spmm_elu_kernel(float* __restrict__ out, int N) {
    int warp = (blockIdx.x * blockDim.x + threadIdx.x) >> 5;
    int lane = threadIdx.x & 31;
    if (warp >= N) return;

    int start = g_rowptr[warp];
    int end   = g_rowptr[warp + 1];

    const uint2* __restrict__ Yh = (const uint2*)g_Yh;
    float4 acc = make_float4(0.f, 0.f, 0.f, 0.f);

    int i = start;
    for (; i + 3 < end; i += 4) {
        int2 e0 = g_edge[i];
        int2 e1 = g_edge[i + 1];
        int2 e2 = g_edge[i + 2];
        int2 e3 = g_edge[i + 3];
        uint2 r0 = Yh[(size_t)e0.x * 32 + lane];
        uint2 r1 = Yh[(size_t)e1.x * 32 + lane];
        uint2 r2 = Yh[(size_t)e2.x * 32 + lane];
        uint2 r3 = Yh[(size_t)e3.x * 32 + lane];
        float v0 = __int_as_float(e0.y);
        float v1 = __int_as_float(e1.y);
        float v2 = __int_as_float(e2.y);
        float v3 = __int_as_float(e3.y);
        float2 a0 = __half22float2(*(const __half2*)&r0.x);
        float2 b0 = __half22float2(*(const __half2*)&r0.y);
        float2 a1 = __half22float2(*(const __half2*)&r1.x);
        float2 b1 = __half22float2(*(const __half2*)&r1.y);
        float2 a2 = __half22float2(*(const __half2*)&r2.x);
        float2 b2 = __half22float2(*(const __half2*)&r2.y);
        float2 a3 = __half22float2(*(const __half2*)&r3.x);
        float2 b3 = __half22float2(*(const __half2*)&r3.y);
        acc.x += v0 * a0.x + v1 * a1.x + v2 * a2.x + v3 * a3.x;
        acc.y += v0 * a0.y + v1 * a1.y + v2 * a2.y + v3 * a3.y;
        acc.z += v0 * b0.x + v1 * b1.x + v2 * b2.x + v3 * b3.x;
        acc.w += v0 * b0.y + v1 * b1.y + v2 * b2.y + v3 * b3.y;
    }
    for (; i < end; i++) {
        int2 e0 = g_edge[i];
        uint2 r0 = Yh[(size_t)e0.x * 32 + lane];
        float v0 = __int_as_float(e0.y);
        float2 a0 = __half22float2(*(const __half2*)&r0.x);
        float2 b0 = __half22float2(*(const __half2*)&r0.y);
        acc.x += v0 * a0.x;
        acc.y += v0 * a0.y;
        acc.z += v0 * b0.x;
        acc.w += v0 * b0.y;
    }

    acc.x = acc.x > 0.f ? acc.x : expm1f(acc.x);
    acc.y = acc.y > 0.f ? acc.y : expm1f(acc.y);
    acc.z = acc.z > 0.f ? acc.z : expm1f(acc.z);
    acc.w = acc.w > 0.f ? acc.w : expm1f(acc.w);

    ((float4*)out)[(size_t)warp * 32 + lane] = acc;
}

// ---------------- launch ---------------------------------------------------------
extern "C" void kernel_launch(void* const* d_in, const int* in_sizes, int n_in,
                              void* d_out, int out_size) {
    const float* x    = (const float*)d_in[0];
    const float* W    = (const float*)d_in[1];
    const float* b    = (const float*)d_in[2];
    const int*   rows = (const int*)d_in[3];
    const int*   cols = (const int*)d_in[4];
    const float* vals = (const float*)d_in[5];
    float* out = (float*)d_out;

    int N = in_sizes[0] / DIM;
    int E = in_sizes[3];
    int nb = (N + STILE - 1) / STILE;
    int e4 = (E + 3) / 4;

    cudaStream_t s1;
    cudaStreamCreateWithFlags(&s1, cudaStreamNonBlocking);
    cudaEvent_t evFork, evJoin;
    cudaEventCreateWithFlags(&evFork, cudaEventDisableTiming);
    cudaEventCreateWithFlags(&evJoin, cudaEventDisableTiming);

    cudaEventRecord(evFork, 0);
    cudaStreamWaitEvent(s1, evFork, 0);

    // CSR build chain on side stream
    zero_cnt_kernel<<<(N + 255) / 256, 256, 0, s1>>>(N);
    hist_kernel<<<(e4 + 255) / 256, 256, 0, s1>>>(rows, E);
    reduce_tile_kernel<<<nb, 256, 0, s1>>>(N);
    scan_tops_kernel<<<1, 128, 0, s1>>>(nb, N);
    scan_tile_kernel<<<nb, STILE, 0, s1>>>(N);
    scatter_kernel<<<(e4 + 255) / 256, 256, 0, s1>>>(rows, cols, vals, E);

    // GEMM (fp16 tensor cores, smem-staged) on main stream
    gemm_h_kernel<<<(N + 63) / 64, 256>>>(x, W, b, N);

    cudaEventRecord(evJoin, s1);
    cudaStreamWaitEvent(0, evJoin, 0);

    spmm_elu_kernel<<<((size_t)N * 32 + 255) / 256, 256>>>(out, N);
}